// round 1
// baseline (speedup 1.0000x reference)
#include <cuda_runtime.h>

namespace {
constexpr int NB = 32, C = 64, H = 112, W = 112;
constexpr int HW = H * W;          // 12544
constexpr int CHW = C * HW;
constexpr int H_TILE = 2;
constexpr int TW = W + 2;          // 114 (even -> float2-aligned rows)
constexpr int CI_CHUNK = 8;
constexpr int N_CHUNK = C / CI_CHUNK;   // 8
constexpr int WSM_N = CI_CHUNK * 9 * C; // 4608 floats
constexpr float DELTA = 0.3f;
constexpr float EPS = 1e-5f;
}

// Scratch (allocation-free: __device__ globals)
__device__ float g_y1[NB * C * H * W];   // conv1 raw output (~103 MB)
__device__ float g_q1t[C * 9 * C];       // ternarized w1, layout [(ci*9+k)][co]
__device__ float g_q2t[C * 9 * C];
__device__ float g_stat[4][C];           // sum1, sq1, sum2, sq2
__device__ float g_scale[2][C];
__device__ float g_shift[2][C];

__device__ __forceinline__ unsigned long long pack2(float lo, float hi) {
  unsigned long long r;
  asm("mov.b64 %0, {%1, %2};" : "=l"(r) : "f"(lo), "f"(hi));
  return r;
}
__device__ __forceinline__ void fma2(unsigned long long& d, unsigned long long a,
                                     unsigned long long b) {
  asm("fma.rn.f32x2 %0, %1, %2, %0;" : "+l"(d) : "l"(a), "l"(b));
}
__device__ __forceinline__ float2 unpack2(unsigned long long v) {
  float lo, hi;
  asm("mov.b64 {%0, %1}, %2;" : "=f"(lo), "=f"(hi) : "l"(v));
  return make_float2(lo, hi);
}

// Ternarize + transpose weights; zero stat accumulators (graph replays need this).
__global__ void k_prep(const float* __restrict__ w1, const float* __restrict__ w2) {
  int i = blockIdx.x * blockDim.x + threadIdx.x;
  if (i < 4 * C) ((float*)g_stat)[i] = 0.f;
  if (i < C * C * 9) {
    int co = i / 576, r = i % 576;  // r = ci*9 + k
    float v = w1[i];
    g_q1t[r * C + co] = (fabsf(v) > DELTA) ? (v > 0.f ? 1.f : -1.f) : 0.f;
    v = w2[i];
    g_q2t[r * C + co] = (fabsf(v) > DELTA) ? (v > 0.f ? 1.f : -1.f) : 0.f;
  }
}

// Direct 3x3 conv, fused BN-stats. PASS 0: in=x raw, out=g_y1.
// PASS 1: in=g_y1 with BN1+hardtanh applied on SMEM fill, +residual x, out=dout.
template <int PASS>
__global__ __launch_bounds__(256, 2) void k_conv(const float* __restrict__ x,
                                                 float* __restrict__ dout) {
  __shared__ __align__(16) float xs[CI_CHUNK][H_TILE + 2][TW];
  __shared__ __align__(16) float wsm[WSM_N];
  __shared__ float ssum[C], ssq[C];

  const float* in = (PASS == 0) ? x : g_y1;
  const float* qt = (PASS == 0) ? g_q1t : g_q2t;
  float* out = (PASS == 0) ? g_y1 : dout;

  const int tid = threadIdx.x;
  const int cg = tid & 15;          // co group: co = cg*4 + i
  const int wg = (tid >> 4) & 7;    // w strip:  w0 = wg*14
  const int hh = tid >> 7;          // 0..1 within h tile
  const int n = blockIdx.x / (H / H_TILE);
  const int h0 = (blockIdx.x % (H / H_TILE)) * H_TILE;
  const int w0 = wg * 14;

  if (tid < C) { ssum[tid] = 0.f; ssq[tid] = 0.f; }

  unsigned long long acc[4][7];
#pragma unroll
  for (int i = 0; i < 4; ++i)
#pragma unroll
    for (int t = 0; t < 7; ++t) acc[i][t] = 0ull;

  const float* inb = in + (long long)n * CHW;

  for (int chunk = 0; chunk < N_CHUNK; ++chunk) {
    __syncthreads();
    // weight chunk -> SMEM (coalesced; layout [(ci*9+k)][64co])
#pragma unroll 4
    for (int i = tid; i < WSM_N; i += 256) wsm[i] = qt[chunk * WSM_N + i];
    // x tile -> SMEM with halo + zero padding (BN1+hardtanh fused for PASS 1)
    constexpr int XS_N = CI_CHUNK * (H_TILE + 2) * TW;
    for (int i = tid; i < XS_N; i += 256) {
      int ci = i / ((H_TILE + 2) * TW);
      int rr = i % ((H_TILE + 2) * TW);
      int r = rr / TW, col = rr % TW;
      int h = h0 - 1 + r, w = col - 1;
      float v = 0.f;
      if ((unsigned)h < (unsigned)H && (unsigned)w < (unsigned)W) {
        int cglob = chunk * CI_CHUNK + ci;
        v = inb[cglob * HW + h * W + w];
        if (PASS == 1) {
          v = v * g_scale[0][cglob] + g_shift[0][cglob];
          v = fminf(fmaxf(v, -1.f), 1.f);
        }
      }
      (&xs[0][0][0])[i] = v;
    }
    __syncthreads();

#pragma unroll 1
    for (int ci = 0; ci < CI_CHUNK; ++ci) {
      const float4* wrow = (const float4*)&wsm[ci * 9 * C];
#pragma unroll
      for (int kh = 0; kh < 3; ++kh) {
        const float* row = &xs[ci][hh + kh][w0];  // element offset even -> 8B aligned
        float2 v[8];
#pragma unroll
        for (int t = 0; t < 8; ++t) v[t] = *(const float2*)(row + 2 * t);
        unsigned long long p0[8], p1[7];
#pragma unroll
        for (int t = 0; t < 8; ++t) p0[t] = pack2(v[t].x, v[t].y);
#pragma unroll
        for (int t = 0; t < 7; ++t) p1[t] = pack2(v[t].y, v[t + 1].x);
#pragma unroll
        for (int kw = 0; kw < 3; ++kw) {
          float4 w4 = wrow[(kh * 3 + kw) * (C / 4) + cg];  // conflict-free LDS.128
          unsigned long long wa = pack2(w4.x, w4.x);
          unsigned long long wb = pack2(w4.y, w4.y);
          unsigned long long wc = pack2(w4.z, w4.z);
          unsigned long long wd = pack2(w4.w, w4.w);
#pragma unroll
          for (int t = 0; t < 7; ++t) {
            unsigned long long xx = (kw == 0) ? p0[t] : (kw == 1) ? p1[t] : p0[t + 1];
            fma2(acc[0][t], xx, wa);
            fma2(acc[1][t], xx, wb);
            fma2(acc[2][t], xx, wc);
            fma2(acc[3][t], xx, wd);
          }
        }
      }
    }
  }

  // Epilogue: residual (PASS 1), write, per-channel stats.
  const int h = h0 + hh;
#pragma unroll
  for (int i = 0; i < 4; ++i) {
    int co = cg * 4 + i;
    long long base = (long long)n * CHW + co * HW + h * W + w0;
    float s = 0.f, s2 = 0.f;
#pragma unroll
    for (int t = 0; t < 7; ++t) {
      float2 vv = unpack2(acc[i][t]);
      if (PASS == 1) {
        float2 r = *(const float2*)(x + base + 2 * t);
        vv.x += r.x;
        vv.y += r.y;
      }
      s += vv.x + vv.y;
      s2 += vv.x * vv.x + vv.y * vv.y;
      *(float2*)(out + base + 2 * t) = vv;
    }
    atomicAdd(&ssum[co], s);
    atomicAdd(&ssq[co], s2);
  }
  __syncthreads();
  if (tid < C) {
    atomicAdd(&g_stat[PASS * 2][tid], ssum[tid]);
    atomicAdd(&g_stat[PASS * 2 + 1][tid], ssq[tid]);
  }
}

template <int PASS>
__global__ void k_finalize(const float* __restrict__ g, const float* __restrict__ b) {
  int c = threadIdx.x;
  if (c < C) {
    const float inv = 1.f / (float)(NB * HW);
    float m = g_stat[PASS * 2][c] * inv;
    float var = fmaxf(g_stat[PASS * 2 + 1][c] * inv - m * m, 0.f);
    float s = g[c] * rsqrtf(var + EPS);
    g_scale[PASS][c] = s;
    g_shift[PASS][c] = b[c] - m * s;
  }
}

// In-place BN2 apply + hardtanh on d_out, float4 vectorized (HW % 4 == 0).
__global__ void k_bn2(float* __restrict__ io) {
  int i = blockIdx.x * blockDim.x + threadIdx.x;  // float4 index
  int c = ((i * 4) / HW) % C;
  float4 v = ((float4*)io)[i];
  float s = g_scale[1][c], t = g_shift[1][c];
  v.x = fminf(fmaxf(v.x * s + t, -1.f), 1.f);
  v.y = fminf(fmaxf(v.y * s + t, -1.f), 1.f);
  v.z = fminf(fmaxf(v.z * s + t, -1.f), 1.f);
  v.w = fminf(fmaxf(v.w * s + t, -1.f), 1.f);
  ((float4*)io)[i] = v;
}

extern "C" void kernel_launch(void* const* d_in, const int* in_sizes, int n_in,
                              void* d_out, int out_size) {
  const float* x = (const float*)d_in[0];
  const float* w1 = (const float*)d_in[1];
  const float* g1 = (const float*)d_in[2];
  const float* b1 = (const float*)d_in[3];
  const float* w2 = (const float*)d_in[4];
  const float* g2 = (const float*)d_in[5];
  const float* b2 = (const float*)d_in[6];
  float* out = (float*)d_out;

  const int conv_grid = NB * (H / H_TILE);  // 1792
  k_prep<<<144, 256>>>(w1, w2);
  k_conv<0><<<conv_grid, 256>>>(x, out);
  k_finalize<0><<<1, 64>>>(g1, b1);
  k_conv<1><<<conv_grid, 256>>>(x, out);
  k_finalize<1><<<1, 64>>>(g2, b2);
  k_bn2<<<(NB * CHW) / 4 / 256, 256>>>(out);
}

// round 2
// speedup vs baseline: 1.1778x; 1.1778x over previous
#include <cuda_runtime.h>

namespace {
constexpr int NB = 32, C = 64, H = 112, W = 112;
constexpr int HW = H * W;          // 12544
constexpr int CHW = C * HW;
constexpr int H_TILE = 2;
constexpr int CI_CHUNK = 8;
constexpr int N_CHUNK = C / CI_CHUNK;   // 8
constexpr int WSM_N = CI_CHUNK * 9 * C; // 4608 floats
constexpr int XS_PAIRS = CI_CHUNK * 4 * 128;  // 4096 duplicated pairs
constexpr int XS_BYTES = XS_PAIRS * 8;        // 32768
constexpr int WSM_BYTES = WSM_N * 4;          // 18432
constexpr int SMEM_TOTAL = XS_BYTES + WSM_BYTES + 2 * C * 4;  // 51712
constexpr float DELTA = 0.3f;
constexpr float EPS = 1e-5f;
}

// Scratch (allocation-free: __device__ globals)
__device__ float g_y1[NB * C * H * W];   // conv1 raw output (~103 MB)
__device__ float g_q1t[C * 9 * C];       // ternarized w1, layout [(ci*9+k)][co]
__device__ float g_q2t[C * 9 * C];
__device__ float g_stat[4][C];           // sum1, sq1, sum2, sq2
__device__ float g_scale[2][C];
__device__ float g_shift[2][C];

__device__ __forceinline__ void fma2(unsigned long long& d, unsigned long long a,
                                     unsigned long long b) {
  asm("fma.rn.f32x2 %0, %1, %2, %0;" : "+l"(d) : "l"(a), "l"(b));
}
__device__ __forceinline__ float2 unpack2(unsigned long long v) {
  float lo, hi;
  asm("mov.b64 {%0, %1}, %2;" : "=f"(lo), "=f"(hi) : "l"(v));
  return make_float2(lo, hi);
}

// Ternarize + transpose weights; zero stat accumulators (graph replays need this).
__global__ void k_prep(const float* __restrict__ w1, const float* __restrict__ w2) {
  int i = blockIdx.x * blockDim.x + threadIdx.x;
  if (i < 4 * C) ((float*)g_stat)[i] = 0.f;
  if (i < C * C * 9) {
    int co = i / 576, r = i % 576;  // r = ci*9 + k
    float v = w1[i];
    g_q1t[r * C + co] = (fabsf(v) > DELTA) ? (v > 0.f ? 1.f : -1.f) : 0.f;
    v = w2[i];
    g_q2t[r * C + co] = (fabsf(v) > DELTA) ? (v > 0.f ? 1.f : -1.f) : 0.f;
  }
}

// Direct 3x3 conv, fused BN-stats. PASS 0: in=x raw, out=g_y1.
// PASS 1: in=g_y1 with BN1+hardtanh applied on SMEM fill, +residual x, out=dout.
// SMEM x tile is stored DUPLICATED: each value v held as float2(v,v), so every
// FFMA2 x-operand is a direct ld.shared with no register repacking.
// Accumulator pairs span (co, co+1); weight pairs load naturally from [tap][co].
template <int PASS>
__global__ __launch_bounds__(256, 2) void k_conv(const float* __restrict__ x,
                                                 float* __restrict__ dout) {
  extern __shared__ char smem_raw[];
  float2* xs = (float2*)smem_raw;                      // [CI_CHUNK][4][128] dup pairs
  float* wsm = (float*)(smem_raw + XS_BYTES);          // [CI_CHUNK*9][64]
  float* ssum = (float*)(smem_raw + XS_BYTES + WSM_BYTES);
  float* ssq = ssum + C;

  const float* in = (PASS == 0) ? x : g_y1;
  const float* qt = (PASS == 0) ? g_q1t : g_q2t;
  float* out = (PASS == 0) ? g_y1 : dout;

  const int tid = threadIdx.x;
  const int cg = tid & 15;          // co group: co = cg*4 + i
  const int wg = (tid >> 4) & 7;    // w strip:  w0 = wg*14
  const int hh = tid >> 7;          // 0..1 within h tile
  const int n = blockIdx.x / (H / H_TILE);
  const int h0 = (blockIdx.x % (H / H_TILE)) * H_TILE;
  const int w0 = wg * 14;

  if (tid < C) { ssum[tid] = 0.f; ssq[tid] = 0.f; }

  // acc0[t] = (out[4cg][w0+t], out[4cg+1][w0+t]); acc1 = co 4cg+2,4cg+3
  unsigned long long acc0[14], acc1[14];
#pragma unroll
  for (int t = 0; t < 14; ++t) { acc0[t] = 0ull; acc1[t] = 0ull; }

  const float* inb = in + (long long)n * CHW;
  const unsigned xs_sh = (unsigned)__cvta_generic_to_shared(xs);
  const unsigned wsm_sh = (unsigned)__cvta_generic_to_shared(wsm);

  for (int chunk = 0; chunk < N_CHUNK; ++chunk) {
    __syncthreads();
    // weight chunk -> SMEM (coalesced; layout [(ci*9+k)][64co])
#pragma unroll 4
    for (int i = tid; i < WSM_N; i += 256) wsm[i] = qt[chunk * WSM_N + i];
    // x tile -> SMEM duplicated, halo + zero pad. Pair index p <-> input w = p-1.
    // Pure bit-op indexing: i = ((ci*4 + r)*128 + p).
#pragma unroll
    for (int k = 0; k < XS_PAIRS / 256; ++k) {
      int i = tid + k * 256;
      int ci = i >> 9, r = (i >> 7) & 3, p = i & 127;
      int h = h0 - 1 + r, w = p - 1;
      float v = 0.f;
      if (((unsigned)h < (unsigned)H) & ((unsigned)w < (unsigned)W)) {
        int cglob = chunk * CI_CHUNK + ci;
        v = inb[cglob * HW + h * W + w];
        if (PASS == 1) {
          v = v * g_scale[0][cglob] + g_shift[0][cglob];
          v = fminf(fmaxf(v, -1.f), 1.f);
        }
      }
      xs[i] = make_float2(v, v);
    }
    __syncthreads();

#pragma unroll 1
    for (int ci = 0; ci < CI_CHUNK; ++ci) {
#pragma unroll
      for (int kh = 0; kh < 3; ++kh) {
        // 16 duplicated x pairs covering taps for outputs w0..w0+13
        unsigned raddr = xs_sh + (((ci * 4 + hh + kh) << 7) + w0) * 8u;
        unsigned long long xd[16];
#pragma unroll
        for (int j = 0; j < 8; ++j)
          asm("ld.shared.v2.u64 {%0,%1}, [%2];"
              : "=l"(xd[2 * j]), "=l"(xd[2 * j + 1])
              : "r"(raddr + 16u * j));
        // 3 taps x 4 co weights: one LDS.128 per tap, conflict-free
        unsigned waddr = wsm_sh + ((ci * 9 + kh * 3) * C + 4 * cg) * 4u;
        unsigned long long w01[3], w23[3];
#pragma unroll
        for (int kw = 0; kw < 3; ++kw)
          asm("ld.shared.v2.u64 {%0,%1}, [%2];"
              : "=l"(w01[kw]), "=l"(w23[kw])
              : "r"(waddr + kw * (C * 4u)));
#pragma unroll
        for (int kw = 0; kw < 3; ++kw)
#pragma unroll
          for (int t = 0; t < 14; ++t) {
            fma2(acc0[t], xd[t + kw], w01[kw]);
            fma2(acc1[t], xd[t + kw], w23[kw]);
          }
      }
    }
  }

  // Epilogue: residual (PASS 1), write, per-channel stats.
  const int h = h0 + hh;
#pragma unroll
  for (int i = 0; i < 4; ++i) {
    const unsigned long long* a = (i < 2) ? acc0 : acc1;
    const bool hiH = (i & 1) != 0;
    int co = cg * 4 + i;
    long long base = (long long)n * CHW + co * HW + h * W + w0;
    float s = 0.f, s2 = 0.f;
#pragma unroll
    for (int u = 0; u < 7; ++u) {
      float2 pa = unpack2(a[2 * u]);
      float2 pb = unpack2(a[2 * u + 1]);
      float2 vv = make_float2(hiH ? pa.y : pa.x, hiH ? pb.y : pb.x);
      if (PASS == 1) {
        float2 r = *(const float2*)(x + base + 2 * u);
        vv.x += r.x;
        vv.y += r.y;
      }
      s += vv.x + vv.y;
      s2 += vv.x * vv.x + vv.y * vv.y;
      *(float2*)(out + base + 2 * u) = vv;
    }
    atomicAdd(&ssum[co], s);
    atomicAdd(&ssq[co], s2);
  }
  __syncthreads();
  if (tid < C) {
    atomicAdd(&g_stat[PASS * 2][tid], ssum[tid]);
    atomicAdd(&g_stat[PASS * 2 + 1][tid], ssq[tid]);
  }
}

template <int PASS>
__global__ void k_finalize(const float* __restrict__ g, const float* __restrict__ b) {
  int c = threadIdx.x;
  if (c < C) {
    const float inv = 1.f / (float)(NB * HW);
    float m = g_stat[PASS * 2][c] * inv;
    float var = fmaxf(g_stat[PASS * 2 + 1][c] * inv - m * m, 0.f);
    float s = g[c] * rsqrtf(var + EPS);
    g_scale[PASS][c] = s;
    g_shift[PASS][c] = b[c] - m * s;
  }
}

// In-place BN2 apply + hardtanh on d_out, float4 vectorized (HW % 4 == 0).
__global__ void k_bn2(float* __restrict__ io) {
  int i = blockIdx.x * blockDim.x + threadIdx.x;  // float4 index
  int c = ((i * 4) / HW) % C;
  float4 v = ((float4*)io)[i];
  float s = g_scale[1][c], t = g_shift[1][c];
  v.x = fminf(fmaxf(v.x * s + t, -1.f), 1.f);
  v.y = fminf(fmaxf(v.y * s + t, -1.f), 1.f);
  v.z = fminf(fmaxf(v.z * s + t, -1.f), 1.f);
  v.w = fminf(fmaxf(v.w * s + t, -1.f), 1.f);
  ((float4*)io)[i] = v;
}

extern "C" void kernel_launch(void* const* d_in, const int* in_sizes, int n_in,
                              void* d_out, int out_size) {
  const float* x = (const float*)d_in[0];
  const float* w1 = (const float*)d_in[1];
  const float* g1 = (const float*)d_in[2];
  const float* b1 = (const float*)d_in[3];
  const float* w2 = (const float*)d_in[4];
  const float* g2 = (const float*)d_in[5];
  const float* b2 = (const float*)d_in[6];
  float* out = (float*)d_out;

  // Dynamic smem (51.7 KB/CTA): attribute set is idempotent, not a stream op.
  cudaFuncSetAttribute(k_conv<0>, cudaFuncAttributeMaxDynamicSharedMemorySize, SMEM_TOTAL);
  cudaFuncSetAttribute(k_conv<1>, cudaFuncAttributeMaxDynamicSharedMemorySize, SMEM_TOTAL);

  const int conv_grid = NB * (H / H_TILE);  // 1792
  k_prep<<<144, 256>>>(w1, w2);
  k_conv<0><<<conv_grid, 256, SMEM_TOTAL>>>(x, out);
  k_finalize<0><<<1, 64>>>(g1, b1);
  k_conv<1><<<conv_grid, 256, SMEM_TOTAL>>>(x, out);
  k_finalize<1><<<1, 64>>>(g2, b2);
  k_bn2<<<(NB * CHW) / 4 / 256, 256>>>(out);
}

// round 5
// speedup vs baseline: 3.8494x; 3.2684x over previous
#include <cuda_runtime.h>
#include <cuda_fp16.h>

namespace {
constexpr int NB = 32, C = 64, H = 112, W = 112;
constexpr int HW = H * W;          // 12544
constexpr int CHW = C * HW;
constexpr int HQ = 4;              // output rows per CTA
constexpr int NROW = HQ + 2;       // input row planes
constexpr int PLANE_B = 136 * 128; // 17408 B (17 KB, 1024-aligned rows)
constexpr int X_OFF = 1024;        // planes start (stats below)
constexpr int W_OFF = X_OFF + NROW * PLANE_B;   // 105472
constexpr int WIMG_B = 9 * 64 * 128;            // 73728 B weight image
constexpr int S_OFF = W_OFF + WIMG_B;           // 179200 staging
constexpr int STAGE_LD = 132;                   // f32 pitch, conflict-free scatter
constexpr int SMEM_TOTAL = S_OFF + C * STAGE_LD * 4;  // 212992 B
constexpr float DELTA = 0.3f, EPS = 1e-5f;
}

// Scratch (allocation-free: __device__ globals)
__device__ float g_y1[NB * CHW];                           // conv1 raw output
__device__ __align__(16) unsigned char g_wimg[2][WIMG_B];  // swizzled fp16 weights
__device__ float g_stat[4][C];
__device__ float g_scale[2][C];
__device__ float g_shift[2][C];

__device__ __forceinline__ unsigned sw128(unsigned off) {
  return off ^ ((off >> 3) & 0x70u);
}

__device__ __forceinline__ void ldsm4(unsigned& r0, unsigned& r1, unsigned& r2,
                                      unsigned& r3, unsigned addr) {
  asm volatile("ldmatrix.sync.aligned.m8n8.x4.shared.b16 {%0,%1,%2,%3}, [%4];"
               : "=r"(r0), "=r"(r1), "=r"(r2), "=r"(r3) : "r"(addr));
}

__device__ __forceinline__ void mma16816(float* d, unsigned a0, unsigned a1,
                                         unsigned a2, unsigned a3, unsigned b0,
                                         unsigned b1) {
  asm volatile(
      "mma.sync.aligned.m16n8k16.row.col.f32.f16.f16.f32 "
      "{%0,%1,%2,%3}, {%4,%5,%6,%7}, {%8,%9}, {%0,%1,%2,%3};"
      : "+f"(d[0]), "+f"(d[1]), "+f"(d[2]), "+f"(d[3])
      : "r"(a0), "r"(a1), "r"(a2), "r"(a3), "r"(b0), "r"(b1));
}

// Ternarize + build swizzled fp16 weight images [tap][co][ci]; zero stats.
__global__ void k_prep(const float* __restrict__ w1, const float* __restrict__ w2) {
  int i = blockIdx.x * blockDim.x + threadIdx.x;
  if (i < 4 * C) ((float*)g_stat)[i] = 0.f;
  if (i < C * C * 9) {
    int co = i / 576, r = i % 576, ci = r / 9, k = r % 9;
    unsigned phys = sw128(k * 8192 + co * 128 + ci * 2);
    float v = w1[i];
    float q = (fabsf(v) > DELTA) ? (v > 0.f ? 1.f : -1.f) : 0.f;
    *(__half*)&g_wimg[0][phys] = __float2half_rn(q);
    v = w2[i];
    q = (fabsf(v) > DELTA) ? (v > 0.f ? 1.f : -1.f) : 0.f;
    *(__half*)&g_wimg[1][phys] = __float2half_rn(q);
  }
}

// mma.sync implicit conv. PASS 0: in=x, out=g_y1. PASS 1: in=BN1(g_y1) clipped,
// +residual x in epilogue, out=dout. Per output row: D[pos128][co64] = sum over
// 9 taps of A(plane row shifted) x B(weight tap image), fp16 in / fp32 accum.
template <int PASS>
__global__ __launch_bounds__(512, 1) void k_conv(const float* __restrict__ x,
                                                 float* __restrict__ dout) {
  extern __shared__ __align__(1024) char smem[];
  float* ssum = (float*)smem;           // [0,256)
  float* ssq = (float*)(smem + 256);    // [256,512)
  float* stag = (float*)(smem + S_OFF);
  const unsigned sx = (unsigned)__cvta_generic_to_shared(smem) + X_OFF;
  const unsigned sw = (unsigned)__cvta_generic_to_shared(smem) + W_OFF;

  const int tid = threadIdx.x;
  const int lane = tid & 31, wid = tid >> 5;
  const int n = blockIdx.x / (H / HQ);
  const int h0 = (blockIdx.x % (H / HQ)) * HQ;

  const float* in = (PASS == 0) ? x : g_y1;
  float* out = (PASS == 0) ? g_y1 : dout;

  if (tid < 2 * C) ssum[tid] = 0.f;  // covers ssum+ssq

  // ---- convert: 6 input rows fp32 NCHW -> fp16 swizzled [pos][ci] planes ----
  const float* inb = in + (long long)n * CHW;
  for (int idx = tid; idx < NROW * (C / 2) * (W / 4); idx += 512) {
    int r = idx / ((C / 2) * (W / 4));
    int rem = idx % ((C / 2) * (W / 4));
    int ci = (rem / (W / 4)) * 2;
    int w0 = (rem % (W / 4)) * 4;
    int h = h0 - 1 + r;
    float4 a = make_float4(0.f, 0.f, 0.f, 0.f), b = a;
    if ((unsigned)h < (unsigned)H) {
      a = *(const float4*)(inb + ci * HW + h * W + w0);
      b = *(const float4*)(inb + (ci + 1) * HW + h * W + w0);
      if (PASS == 1) {
        float s0 = g_scale[0][ci], t0 = g_shift[0][ci];
        float s1 = g_scale[0][ci + 1], t1 = g_shift[0][ci + 1];
        a.x = fminf(fmaxf(a.x * s0 + t0, -1.f), 1.f);
        a.y = fminf(fmaxf(a.y * s0 + t0, -1.f), 1.f);
        a.z = fminf(fmaxf(a.z * s0 + t0, -1.f), 1.f);
        a.w = fminf(fmaxf(a.w * s0 + t0, -1.f), 1.f);
        b.x = fminf(fmaxf(b.x * s1 + t1, -1.f), 1.f);
        b.y = fminf(fmaxf(b.y * s1 + t1, -1.f), 1.f);
        b.z = fminf(fmaxf(b.z * s1 + t1, -1.f), 1.f);
        b.w = fminf(fmaxf(b.w * s1 + t1, -1.f), 1.f);
      }
    }
    const float av[4] = {a.x, a.y, a.z, a.w};
    const float bv[4] = {b.x, b.y, b.z, b.w};
    char* plane = smem + X_OFF + r * PLANE_B;
#pragma unroll
    for (int j = 0; j < 4; ++j) {
      int p = w0 + j + 1;  // pos p holds input w = p-1
      *(__half2*)(plane + sw128(p * 128 + ci * 2)) = __floats2half2_rn(av[j], bv[j]);
    }
  }
  // zero-pad p==0 and p in [113,136)
  for (int idx = tid; idx < NROW * 24 * 8; idx += 512) {
    int r = idx / (24 * 8);
    int rem = idx % (24 * 8);
    int pi = rem / 8, k16 = rem % 8;
    int p = (pi == 0) ? 0 : (112 + pi);
    *(uint4*)(smem + X_OFF + r * PLANE_B + sw128(p * 128 + k16 * 16)) =
        make_uint4(0, 0, 0, 0);
  }
  // weight image (pre-swizzled) -> SMEM, linear copy
  {
    const uint4* src = (const uint4*)g_wimg[PASS];
    uint4* dst = (uint4*)(smem + W_OFF);
    for (int i = tid; i < WIMG_B / 16; i += 512) dst[i] = src[i];
  }
  __syncthreads();

  // ---- MMA: warp = 16 pos x 64 co of one row; 2 rows per pass, 2 passes ----
  const int jj = wid >> 3;   // row within pair
  const int pw = wid & 7;    // pos block
  const int p0 = pw * 16;
  // A ldmatrix lane pattern: rows 0-15 = pos, chunk = k-half
  const int arow_l = lane & 15, achunk_l = lane >> 4;
  // B ldmatrix lane pattern: 16 co rows x 2 k-chunks
  const int brow_l = (lane & 7) + ((lane >> 4) << 3), bchunk_l = (lane >> 3) & 1;

#pragma unroll 1
  for (int jp = 0; jp < 2; ++jp) {
    const int j = jp * 2 + jj;
    float d[8][4];
#pragma unroll
    for (int t = 0; t < 8; ++t)
#pragma unroll
      for (int q = 0; q < 4; ++q) d[t][q] = 0.f;

#pragma unroll
    for (int kh = 0; kh < 3; ++kh) {
#pragma unroll
      for (int kw = 0; kw < 3; ++kw) {
        const unsigned abase = (j + kh) * PLANE_B;
        const unsigned bbase = (kh * 3 + kw) * 8192;
#pragma unroll
        for (int s = 0; s < 4; ++s) {
          unsigned a0, a1, a2, a3;
          unsigned aoff = abase + (p0 + kw + arow_l) * 128 + s * 32 + achunk_l * 16;
          ldsm4(a0, a1, a2, a3, sx + sw128(aoff));
#pragma unroll
          for (int t2 = 0; t2 < 4; ++t2) {
            unsigned b0, b1, b2, b3;
            unsigned boff = bbase + (t2 * 16 + brow_l) * 128 + s * 32 + bchunk_l * 16;
            ldsm4(b0, b1, b2, b3, sw + sw128(boff));
            mma16816(d[2 * t2], a0, a1, a2, a3, b0, b1);
            mma16816(d[2 * t2 + 1], a0, a1, a2, a3, b2, b3);
          }
        }
      }
    }

    // ---- epilogue via staging (serialize the two row-groups) ----
#pragma unroll 1
    for (int phase = 0; phase < 2; ++phase) {
      if (jj == phase) {
        int prow = p0 + (lane >> 2);
        int cb = 2 * (lane & 3);
#pragma unroll
        for (int t = 0; t < 8; ++t) {
          int co = t * 8 + cb;
          stag[co * STAGE_LD + prow] = d[t][0];
          stag[(co + 1) * STAGE_LD + prow] = d[t][1];
          stag[co * STAGE_LD + prow + 8] = d[t][2];
          stag[(co + 1) * STAGE_LD + prow + 8] = d[t][3];
        }
      }
      __syncthreads();
      {
        const int jrow = jp * 2 + phase;
        const int h = h0 + jrow;
#pragma unroll
        for (int cc = 0; cc < 4; ++cc) {
          int co = wid * 4 + cc;
          float s = 0.f, s2 = 0.f;
          long long base = (long long)n * CHW + (long long)co * HW + h * W;
#pragma unroll
          for (int k = 0; k < 4; ++k) {
            int pos = lane + k * 32;
            if (pos < W) {
              float v = stag[co * STAGE_LD + pos];
              if (PASS == 1) v += x[base + pos];
              out[base + pos] = v;
              s += v;
              s2 += v * v;
            }
          }
#pragma unroll
          for (int dd = 16; dd > 0; dd >>= 1) {
            s += __shfl_xor_sync(0xFFFFFFFFu, s, dd);
            s2 += __shfl_xor_sync(0xFFFFFFFFu, s2, dd);
          }
          if (lane == 0) {
            atomicAdd(&ssum[co], s);
            atomicAdd(&ssq[co], s2);
          }
        }
      }
      __syncthreads();
    }
  }

  if (tid < C) {
    atomicAdd(&g_stat[PASS * 2][tid], ssum[tid]);
    atomicAdd(&g_stat[PASS * 2 + 1][tid], ssq[tid]);
  }
}

template <int PASS>
__global__ void k_finalize(const float* __restrict__ g, const float* __restrict__ b) {
  int c = threadIdx.x;
  if (c < C) {
    const float inv = 1.f / (float)(NB * HW);
    float m = g_stat[PASS * 2][c] * inv;
    float var = fmaxf(g_stat[PASS * 2 + 1][c] * inv - m * m, 0.f);
    float s = g[c] * rsqrtf(var + EPS);
    g_scale[PASS][c] = s;
    g_shift[PASS][c] = b[c] - m * s;
  }
}

__global__ void k_bn2(float* __restrict__ io) {
  int i = blockIdx.x * blockDim.x + threadIdx.x;
  int c = ((i * 4) / HW) % C;
  float4 v = ((float4*)io)[i];
  float s = g_scale[1][c], t = g_shift[1][c];
  v.x = fminf(fmaxf(v.x * s + t, -1.f), 1.f);
  v.y = fminf(fmaxf(v.y * s + t, -1.f), 1.f);
  v.z = fminf(fmaxf(v.z * s + t, -1.f), 1.f);
  v.w = fminf(fmaxf(v.w * s + t, -1.f), 1.f);
  ((float4*)io)[i] = v;
}

extern "C" void kernel_launch(void* const* d_in, const int* in_sizes, int n_in,
                              void* d_out, int out_size) {
  const float* x = (const float*)d_in[0];
  const float* w1 = (const float*)d_in[1];
  const float* g1 = (const float*)d_in[2];
  const float* b1 = (const float*)d_in[3];
  const float* w2 = (const float*)d_in[4];
  const float* g2 = (const float*)d_in[5];
  const float* b2 = (const float*)d_in[6];
  float* out = (float*)d_out;

  cudaFuncSetAttribute(k_conv<0>, cudaFuncAttributeMaxDynamicSharedMemorySize, SMEM_TOTAL);
  cudaFuncSetAttribute(k_conv<1>, cudaFuncAttributeMaxDynamicSharedMemorySize, SMEM_TOTAL);

  const int grid = NB * (H / HQ);  // 896
  k_prep<<<144, 256>>>(w1, w2);
  k_conv<0><<<grid, 512, SMEM_TOTAL>>>(x, out);
  k_finalize<0><<<1, 64>>>(g1, b1);
  k_conv<1><<<grid, 512, SMEM_TOTAL>>>(x, out);
  k_finalize<1><<<1, 64>>>(g2, b2);
  k_bn2<<<(NB * CHW) / 4 / 256, 256>>>(out);
}

// round 6
// speedup vs baseline: 4.0604x; 1.0548x over previous
#include <cuda_runtime.h>
#include <cuda_fp16.h>

namespace {
constexpr int NB = 32, C = 64, H = 112, W = 112;
constexpr int HW = H * W;          // 12544
constexpr int CHW = C * HW;
constexpr int HQ = 4;              // output rows per CTA
constexpr int NROW = HQ + 2;       // input row planes
constexpr int PLANE_B = 136 * 128; // 17408 B (17 KB, 1024-aligned rows)
constexpr int X_OFF = 1024;        // planes start (stats below)
constexpr int W_OFF = X_OFF + NROW * PLANE_B;   // 105472
constexpr int WIMG_B = 9 * 64 * 128;            // 73728 B weight image
constexpr int S_OFF = W_OFF + WIMG_B;           // 179200 staging
constexpr int STAGE_LD = 132;                   // f32 pitch, conflict-free scatter
constexpr int SMEM_TOTAL = S_OFF + C * STAGE_LD * 4;  // 212992 B
constexpr float DELTA = 0.3f, EPS = 1e-5f;
}

// Scratch (allocation-free: __device__ globals)
__device__ float g_y1[NB * CHW];                           // conv1 raw output
__device__ __align__(16) unsigned char g_wimg[2][WIMG_B];  // swizzled fp16 weights
__device__ float g_stat[4][C];
__device__ float g_scale[2][C];
__device__ float g_shift[2][C];

__device__ __forceinline__ unsigned sw128(unsigned off) {
  return off ^ ((off >> 3) & 0x70u);
}

__device__ __forceinline__ void ldsm4(unsigned& r0, unsigned& r1, unsigned& r2,
                                      unsigned& r3, unsigned addr) {
  asm volatile("ldmatrix.sync.aligned.m8n8.x4.shared.b16 {%0,%1,%2,%3}, [%4];"
               : "=r"(r0), "=r"(r1), "=r"(r2), "=r"(r3) : "r"(addr));
}

__device__ __forceinline__ void mma16816(float* d, unsigned a0, unsigned a1,
                                         unsigned a2, unsigned a3, unsigned b0,
                                         unsigned b1) {
  asm volatile(
      "mma.sync.aligned.m16n8k16.row.col.f32.f16.f16.f32 "
      "{%0,%1,%2,%3}, {%4,%5,%6,%7}, {%8,%9}, {%0,%1,%2,%3};"
      : "+f"(d[0]), "+f"(d[1]), "+f"(d[2]), "+f"(d[3])
      : "r"(a0), "r"(a1), "r"(a2), "r"(a3), "r"(b0), "r"(b1));
}

// Ternarize + build swizzled fp16 weight images [tap][co][ci]; zero stats.
__global__ void k_prep(const float* __restrict__ w1, const float* __restrict__ w2) {
  int i = blockIdx.x * blockDim.x + threadIdx.x;
  if (i < 4 * C) ((float*)g_stat)[i] = 0.f;
  if (i < C * C * 9) {
    int co = i / 576, r = i % 576, ci = r / 9, k = r % 9;
    unsigned phys = sw128(k * 8192 + co * 128 + ci * 2);
    float v = w1[i];
    float q = (fabsf(v) > DELTA) ? (v > 0.f ? 1.f : -1.f) : 0.f;
    *(__half*)&g_wimg[0][phys] = __float2half_rn(q);
    v = w2[i];
    q = (fabsf(v) > DELTA) ? (v > 0.f ? 1.f : -1.f) : 0.f;
    *(__half*)&g_wimg[1][phys] = __float2half_rn(q);
  }
}

// mma.sync implicit conv. Warp tile = 32 pos x 64 co (0.375 ldsm/MMA); 16 warps
// cover all 4 output rows in one pass (no B-fragment reload across row passes).
// PASS 0: in=x, out=g_y1. PASS 1: in=BN1(g_y1) clipped, +residual, out=dout.
template <int PASS>
__global__ __launch_bounds__(512, 1) void k_conv(const float* __restrict__ x,
                                                 float* __restrict__ dout) {
  extern __shared__ __align__(1024) char smem[];
  float* ssum = (float*)smem;           // [0,256)
  float* ssq = (float*)(smem + 256);    // [256,512)
  float* stag = (float*)(smem + S_OFF);
  const unsigned sx = (unsigned)__cvta_generic_to_shared(smem) + X_OFF;
  const unsigned sw = (unsigned)__cvta_generic_to_shared(smem) + W_OFF;

  const int tid = threadIdx.x;
  const int lane = tid & 31, wid = tid >> 5;
  const int n = blockIdx.x / (H / HQ);
  const int h0 = (blockIdx.x % (H / HQ)) * HQ;

  const float* in = (PASS == 0) ? x : g_y1;
  float* out = (PASS == 0) ? g_y1 : dout;

  if (tid < 2 * C) ssum[tid] = 0.f;  // covers ssum+ssq

  // ---- convert: 6 input rows fp32 NCHW -> fp16 swizzled [pos][ci] planes ----
  const float* inb = in + (long long)n * CHW;
  for (int idx = tid; idx < NROW * (C / 2) * (W / 4); idx += 512) {
    int r = idx / ((C / 2) * (W / 4));
    int rem = idx % ((C / 2) * (W / 4));
    int ci = (rem / (W / 4)) * 2;
    int w0 = (rem % (W / 4)) * 4;
    int h = h0 - 1 + r;
    float4 a = make_float4(0.f, 0.f, 0.f, 0.f), b = a;
    if ((unsigned)h < (unsigned)H) {
      a = *(const float4*)(inb + ci * HW + h * W + w0);
      b = *(const float4*)(inb + (ci + 1) * HW + h * W + w0);
      if (PASS == 1) {
        float s0 = g_scale[0][ci], t0 = g_shift[0][ci];
        float s1 = g_scale[0][ci + 1], t1 = g_shift[0][ci + 1];
        a.x = fminf(fmaxf(a.x * s0 + t0, -1.f), 1.f);
        a.y = fminf(fmaxf(a.y * s0 + t0, -1.f), 1.f);
        a.z = fminf(fmaxf(a.z * s0 + t0, -1.f), 1.f);
        a.w = fminf(fmaxf(a.w * s0 + t0, -1.f), 1.f);
        b.x = fminf(fmaxf(b.x * s1 + t1, -1.f), 1.f);
        b.y = fminf(fmaxf(b.y * s1 + t1, -1.f), 1.f);
        b.z = fminf(fmaxf(b.z * s1 + t1, -1.f), 1.f);
        b.w = fminf(fmaxf(b.w * s1 + t1, -1.f), 1.f);
      }
    }
    const float av[4] = {a.x, a.y, a.z, a.w};
    const float bv[4] = {b.x, b.y, b.z, b.w};
    char* plane = smem + X_OFF + r * PLANE_B;
#pragma unroll
    for (int j = 0; j < 4; ++j) {
      int p = w0 + j + 1;  // pos p holds input w = p-1
      *(__half2*)(plane + sw128(p * 128 + ci * 2)) = __floats2half2_rn(av[j], bv[j]);
    }
  }
  // zero-pad p==0 and p in [113,136)
  for (int idx = tid; idx < NROW * 24 * 8; idx += 512) {
    int r = idx / (24 * 8);
    int rem = idx % (24 * 8);
    int pi = rem / 8, k16 = rem % 8;
    int p = (pi == 0) ? 0 : (112 + pi);
    *(uint4*)(smem + X_OFF + r * PLANE_B + sw128(p * 128 + k16 * 16)) =
        make_uint4(0, 0, 0, 0);
  }
  // weight image (pre-swizzled) -> SMEM, linear copy
  {
    const uint4* src = (const uint4*)g_wimg[PASS];
    uint4* dst = (uint4*)(smem + W_OFF);
    for (int i = tid; i < WIMG_B / 16; i += 512) dst[i] = src[i];
  }
  __syncthreads();

  // ---- MMA: warp = 32 pos x 64 co of one row; 16 warps = 4 rows x 4 pos-grps ----
  const int row = wid >> 2;  // output row within CTA
  const int p0 = (wid & 3) * 32;
  // A ldmatrix lane pattern: rows 0-15 = pos, chunk = k-half
  const int arow_l = lane & 15, achunk_l = lane >> 4;
  // B ldmatrix lane pattern: 16 co rows x 2 k-chunks
  const int brow_l = (lane & 7) + ((lane >> 4) << 3), bchunk_l = (lane >> 3) & 1;

  // d[ap*8 + 2*t2 + half]: ap = pos 16-block, t2 = co 16-block, half = co 8-block
  float d[16][4];
#pragma unroll
  for (int t = 0; t < 16; ++t)
#pragma unroll
    for (int q = 0; q < 4; ++q) d[t][q] = 0.f;

#pragma unroll 1
  for (int kh = 0; kh < 3; ++kh) {
    const unsigned abase = (row + kh) * PLANE_B;
#pragma unroll
    for (int kw = 0; kw < 3; ++kw) {
      const unsigned bbase = (kh * 3 + kw) * 8192;
#pragma unroll
      for (int s = 0; s < 4; ++s) {
        unsigned a0, a1, a2, a3, a4, a5, a6, a7;
        unsigned aoff0 = abase + (p0 + kw + arow_l) * 128 + s * 32 + achunk_l * 16;
        unsigned aoff1 = aoff0 + 16 * 128;
        ldsm4(a0, a1, a2, a3, sx + sw128(aoff0));
        ldsm4(a4, a5, a6, a7, sx + sw128(aoff1));
#pragma unroll
        for (int t2 = 0; t2 < 4; ++t2) {
          unsigned b0, b1, b2, b3;
          unsigned boff = bbase + (t2 * 16 + brow_l) * 128 + s * 32 + bchunk_l * 16;
          ldsm4(b0, b1, b2, b3, sw + sw128(boff));
          mma16816(d[2 * t2], a0, a1, a2, a3, b0, b1);
          mma16816(d[2 * t2 + 1], a0, a1, a2, a3, b2, b3);
          mma16816(d[8 + 2 * t2], a4, a5, a6, a7, b0, b1);
          mma16816(d[8 + 2 * t2 + 1], a4, a5, a6, a7, b2, b3);
        }
      }
    }
  }

  // ---- epilogue via staging: 4 phases, one output row each ----
#pragma unroll 1
  for (int phase = 0; phase < HQ; ++phase) {
    if (row == phase) {
      int cb = 2 * (lane & 3);
#pragma unroll
      for (int ap = 0; ap < 2; ++ap) {
        int prow = p0 + ap * 16 + (lane >> 2);
#pragma unroll
        for (int t = 0; t < 8; ++t) {
          int co = t * 8 + cb;
          stag[co * STAGE_LD + prow] = d[ap * 8 + t][0];
          stag[(co + 1) * STAGE_LD + prow] = d[ap * 8 + t][1];
          stag[co * STAGE_LD + prow + 8] = d[ap * 8 + t][2];
          stag[(co + 1) * STAGE_LD + prow + 8] = d[ap * 8 + t][3];
        }
      }
    }
    __syncthreads();
    {
      const int h = h0 + phase;
#pragma unroll
      for (int cc = 0; cc < 4; ++cc) {
        int co = wid * 4 + cc;
        float s = 0.f, s2 = 0.f;
        long long base = (long long)n * CHW + (long long)co * HW + h * W;
#pragma unroll
        for (int k = 0; k < 4; ++k) {
          int pos = lane + k * 32;
          if (pos < W) {
            float v = stag[co * STAGE_LD + pos];
            if (PASS == 1) v += x[base + pos];
            out[base + pos] = v;
            s += v;
            s2 += v * v;
          }
        }
#pragma unroll
        for (int dd = 16; dd > 0; dd >>= 1) {
          s += __shfl_xor_sync(0xFFFFFFFFu, s, dd);
          s2 += __shfl_xor_sync(0xFFFFFFFFu, s2, dd);
        }
        if (lane == 0) {
          atomicAdd(&ssum[co], s);
          atomicAdd(&ssq[co], s2);
        }
      }
    }
    __syncthreads();
  }

  if (tid < C) {
    atomicAdd(&g_stat[PASS * 2][tid], ssum[tid]);
    atomicAdd(&g_stat[PASS * 2 + 1][tid], ssq[tid]);
  }
}

template <int PASS>
__global__ void k_finalize(const float* __restrict__ g, const float* __restrict__ b) {
  int c = threadIdx.x;
  if (c < C) {
    const float inv = 1.f / (float)(NB * HW);
    float m = g_stat[PASS * 2][c] * inv;
    float var = fmaxf(g_stat[PASS * 2 + 1][c] * inv - m * m, 0.f);
    float s = g[c] * rsqrtf(var + EPS);
    g_scale[PASS][c] = s;
    g_shift[PASS][c] = b[c] - m * s;
  }
}

__global__ void k_bn2(float* __restrict__ io) {
  int i = blockIdx.x * blockDim.x + threadIdx.x;
  int c = ((i * 4) / HW) % C;
  float4 v = ((float4*)io)[i];
  float s = g_scale[1][c], t = g_shift[1][c];
  v.x = fminf(fmaxf(v.x * s + t, -1.f), 1.f);
  v.y = fminf(fmaxf(v.y * s + t, -1.f), 1.f);
  v.z = fminf(fmaxf(v.z * s + t, -1.f), 1.f);
  v.w = fminf(fmaxf(v.w * s + t, -1.f), 1.f);
  ((float4*)io)[i] = v;
}

extern "C" void kernel_launch(void* const* d_in, const int* in_sizes, int n_in,
                              void* d_out, int out_size) {
  const float* x = (const float*)d_in[0];
  const float* w1 = (const float*)d_in[1];
  const float* g1 = (const float*)d_in[2];
  const float* b1 = (const float*)d_in[3];
  const float* w2 = (const float*)d_in[4];
  const float* g2 = (const float*)d_in[5];
  const float* b2 = (const float*)d_in[6];
  float* out = (float*)d_out;

  cudaFuncSetAttribute(k_conv<0>, cudaFuncAttributeMaxDynamicSharedMemorySize, SMEM_TOTAL);
  cudaFuncSetAttribute(k_conv<1>, cudaFuncAttributeMaxDynamicSharedMemorySize, SMEM_TOTAL);

  const int grid = NB * (H / HQ);  // 896
  k_prep<<<144, 256>>>(w1, w2);
  k_conv<0><<<grid, 512, SMEM_TOTAL>>>(x, out);
  k_finalize<0><<<1, 64>>>(g1, b1);
  k_conv<1><<<grid, 512, SMEM_TOTAL>>>(x, out);
  k_finalize<1><<<1, 64>>>(g2, b2);
  k_bn2<<<(NB * CHW) / 4 / 256, 256>>>(out);
}